// round 1
// baseline (speedup 1.0000x reference)
#include <cuda_runtime.h>
#include <math.h>

// ---------------------------------------------------------------------------
// Problem constants
// ---------------------------------------------------------------------------
#define BATCH   8
#define CIN     3
#define HH      512
#define WW      512
#define NF      16
#define FEAT    3
#define NUM_IDS 32
#define EPS     1e-5f

// Biggest intermediate: [8,16,512,512] = 33,554,432 floats (134 MB)
#define BUF_ELEMS (8*16*512*512)

__device__ float g_bufA[BUF_ELEMS];
__device__ float g_bufB[BUF_ELEMS];
__device__ float g_mean[8*256];
__device__ float g_istd[8*256];
__device__ float g_sums[BATCH*NUM_IDS*FEAT];
__device__ float g_cnt [BATCH*NUM_IDS];

static inline int cdiv(int a, int b) { return (a + b - 1) / b; }

// ---------------------------------------------------------------------------
// 7x7 conv with reflect padding 3 (stride 1), optional tanh
// in:  [B, Cin, H, W]   w: [Cout, Cin, 7, 7]   out: [B, Cout, H, W]
// ---------------------------------------------------------------------------
__global__ void conv7_reflect(const float* __restrict__ in,
                              const float* __restrict__ w,
                              const float* __restrict__ bias,
                              float* __restrict__ out,
                              int Cin_, int Cout_, int H, int W, int applyTanh)
{
    int idx = blockIdx.x * blockDim.x + threadIdx.x;
    int total = BATCH * Cout_ * H * W;
    if (idx >= total) return;
    int ox = idx % W;
    int oy = (idx / W) % H;
    int co = (idx / (W * H)) % Cout_;
    int bb = idx / (W * H * Cout_);

    // precompute reflected indices
    int iys[7], ixs[7];
#pragma unroll
    for (int k = 0; k < 7; k++) {
        int iy = oy - 3 + k;
        iys[k] = (iy < 0) ? -iy : ((iy >= H) ? 2 * H - 2 - iy : iy);
        int ix = ox - 3 + k;
        ixs[k] = (ix < 0) ? -ix : ((ix >= W) ? 2 * W - 2 - ix : ix);
    }

    float acc = bias[co];
    for (int ci = 0; ci < Cin_; ci++) {
        const float* ip = in + ((size_t)(bb * Cin_ + ci)) * H * W;
        const float* wp = w + (co * Cin_ + ci) * 49;
#pragma unroll
        for (int ky = 0; ky < 7; ky++) {
            const float* row = ip + (size_t)iys[ky] * W;
#pragma unroll
            for (int kx = 0; kx < 7; kx++) {
                acc += row[ixs[kx]] * wp[ky * 7 + kx];
            }
        }
    }
    if (applyTanh) acc = tanhf(acc);
    out[idx] = acc;
}

// ---------------------------------------------------------------------------
// 3x3 conv, stride 2, zero pad 1
// in: [B, Cin, Hin, Win]  w: [Cout, Cin, 3, 3]  out: [B, Cout, Hin/2, Win/2]
// ---------------------------------------------------------------------------
__global__ void conv3_s2(const float* __restrict__ in,
                         const float* __restrict__ w,
                         const float* __restrict__ bias,
                         float* __restrict__ out,
                         int Cin_, int Cout_, int Hin, int Win)
{
    int Hout = Hin / 2, Wout = Win / 2;
    int idx = blockIdx.x * blockDim.x + threadIdx.x;
    int total = BATCH * Cout_ * Hout * Wout;
    if (idx >= total) return;
    int ox = idx % Wout;
    int oy = (idx / Wout) % Hout;
    int co = (idx / (Wout * Hout)) % Cout_;
    int bb = idx / (Wout * Hout * Cout_);

    int iys[3], ixs[3];
    bool vy[3], vx[3];
#pragma unroll
    for (int k = 0; k < 3; k++) {
        int iy = 2 * oy - 1 + k;
        iys[k] = iy; vy[k] = (iy >= 0 && iy < Hin);
        int ix = 2 * ox - 1 + k;
        ixs[k] = ix; vx[k] = (ix >= 0 && ix < Win);
    }

    float acc = bias[co];
    for (int ci = 0; ci < Cin_; ci++) {
        const float* ip = in + ((size_t)(bb * Cin_ + ci)) * Hin * Win;
        const float* wp = w + (co * Cin_ + ci) * 9;
#pragma unroll
        for (int ky = 0; ky < 3; ky++) {
            if (!vy[ky]) continue;
            const float* row = ip + (size_t)iys[ky] * Win;
#pragma unroll
            for (int kx = 0; kx < 3; kx++) {
                if (!vx[kx]) continue;
                acc += row[ixs[kx]] * wp[ky * 3 + kx];
            }
        }
    }
    out[idx] = acc;
}

// ---------------------------------------------------------------------------
// ConvTranspose2d k=3 s=2 p=1 output_padding=1
// in: [B, Cin, Hin, Win]  w (torch layout): [Cin, Cout, 3, 3]
// out: [B, Cout, 2*Hin, 2*Win]
// out[oy,ox] += w[ci][co][ky][kx] * in[ci][iy][ix]  where 2*iy = oy+1-ky
// ---------------------------------------------------------------------------
__global__ void tconv3_s2(const float* __restrict__ in,
                          const float* __restrict__ w,
                          const float* __restrict__ bias,
                          float* __restrict__ out,
                          int Cin_, int Cout_, int Hin, int Win)
{
    int Hout = 2 * Hin, Wout = 2 * Win;
    int idx = blockIdx.x * blockDim.x + threadIdx.x;
    int total = BATCH * Cout_ * Hout * Wout;
    if (idx >= total) return;
    int ox = idx % Wout;
    int oy = (idx / Wout) % Hout;
    int co = (idx / (Wout * Hout)) % Cout_;
    int bb = idx / (Wout * Hout * Cout_);

    // valid (ky, iy) pairs: at most 2
    int kys[2], iys[2], nky = 0;
#pragma unroll
    for (int ky = 0; ky < 3; ky++) {
        int t = oy + 1 - ky;
        if (t & 1) continue;
        int iy = t >> 1;
        if (iy < 0 || iy >= Hin) continue;
        kys[nky] = ky; iys[nky] = iy; nky++;
    }
    int kxs[2], ixs[2], nkx = 0;
#pragma unroll
    for (int kx = 0; kx < 3; kx++) {
        int s = ox + 1 - kx;
        if (s & 1) continue;
        int ix = s >> 1;
        if (ix < 0 || ix >= Win) continue;
        kxs[nkx] = kx; ixs[nkx] = ix; nkx++;
    }

    float acc = bias[co];
    for (int ci = 0; ci < Cin_; ci++) {
        const float* ip = in + ((size_t)(bb * Cin_ + ci)) * Hin * Win;
        const float* wp = w + ((size_t)(ci * Cout_ + co)) * 9;
        for (int a = 0; a < nky; a++) {
            const float* row = ip + (size_t)iys[a] * Win;
            for (int b2 = 0; b2 < nkx; b2++) {
                acc += row[ixs[b2]] * wp[kys[a] * 3 + kxs[b2]];
            }
        }
    }
    out[idx] = acc;
}

// ---------------------------------------------------------------------------
// InstanceNorm stats: one block per (b, c) channel plane
// ---------------------------------------------------------------------------
__global__ void inorm_stats(const float* __restrict__ x, int HW)
{
    int bc = blockIdx.x;
    const float* p = x + (size_t)bc * HW;
    float s = 0.f, ss = 0.f;
    for (int i = threadIdx.x; i < HW; i += blockDim.x) {
        float v = p[i];
        s += v; ss += v * v;
    }
    __shared__ float sh_s[256], sh_ss[256];
    sh_s[threadIdx.x] = s; sh_ss[threadIdx.x] = ss;
    __syncthreads();
    for (int off = 128; off > 0; off >>= 1) {
        if (threadIdx.x < off) {
            sh_s[threadIdx.x] += sh_s[threadIdx.x + off];
            sh_ss[threadIdx.x] += sh_ss[threadIdx.x + off];
        }
        __syncthreads();
    }
    if (threadIdx.x == 0) {
        float m = sh_s[0] / (float)HW;
        float var = sh_ss[0] / (float)HW - m * m;
        g_mean[bc] = m;
        g_istd[bc] = rsqrtf(var + EPS);
    }
}

// normalize + relu, in place
__global__ void norm_relu(float* __restrict__ x, int HW, int total)
{
    int idx = blockIdx.x * blockDim.x + threadIdx.x;
    if (idx >= total) return;
    int bc = idx / HW;
    float v = (x[idx] - g_mean[bc]) * g_istd[bc];
    x[idx] = v > 0.f ? v : 0.f;
}

// ---------------------------------------------------------------------------
// Instance pooling
// ---------------------------------------------------------------------------
__global__ void pool_zero()
{
    int i = blockIdx.x * blockDim.x + threadIdx.x;
    if (i < BATCH * NUM_IDS * FEAT) g_sums[i] = 0.f;
    if (i < BATCH * NUM_IDS) g_cnt[i] = 0.f;
}

// feat: [B, FEAT, HW], ids: [B, HW]
__global__ void pool_partial(const float* __restrict__ feat,
                             const int* __restrict__ ids, int HW)
{
    __shared__ float s_sum[NUM_IDS * FEAT];
    __shared__ float s_cnt[NUM_IDS];
    for (int i = threadIdx.x; i < NUM_IDS * FEAT; i += blockDim.x) s_sum[i] = 0.f;
    for (int i = threadIdx.x; i < NUM_IDS; i += blockDim.x) s_cnt[i] = 0.f;
    __syncthreads();

    int bb = blockIdx.y;
    for (int p = blockIdx.x * blockDim.x + threadIdx.x; p < HW;
         p += gridDim.x * blockDim.x) {
        int id = ids[(size_t)bb * HW + p];
        atomicAdd(&s_cnt[id], 1.f);
#pragma unroll
        for (int c = 0; c < FEAT; c++) {
            atomicAdd(&s_sum[id * FEAT + c], feat[((size_t)bb * FEAT + c) * HW + p]);
        }
    }
    __syncthreads();
    for (int i = threadIdx.x; i < NUM_IDS * FEAT; i += blockDim.x)
        atomicAdd(&g_sums[bb * NUM_IDS * FEAT + i], s_sum[i]);
    for (int i = threadIdx.x; i < NUM_IDS; i += blockDim.x)
        atomicAdd(&g_cnt[bb * NUM_IDS + i], s_cnt[i]);
}

__global__ void pool_finalize()
{
    int i = blockIdx.x * blockDim.x + threadIdx.x;
    if (i >= BATCH * NUM_IDS) return;
    float c = g_cnt[i];
    float inv = 1.f / fmaxf(c, 1.f);
#pragma unroll
    for (int k = 0; k < FEAT; k++) g_sums[i * FEAT + k] *= inv;
}

__global__ void pool_scatter(const int* __restrict__ ids,
                             float* __restrict__ out, int HW)
{
    int idx = blockIdx.x * blockDim.x + threadIdx.x;
    if (idx >= BATCH * HW) return;
    int p = idx % HW;
    int bb = idx / HW;
    int id = ids[(size_t)bb * HW + p];
#pragma unroll
    for (int c = 0; c < FEAT; c++) {
        out[((size_t)bb * FEAT + c) * HW + p] = g_sums[(bb * NUM_IDS + id) * FEAT + c];
    }
}

// ---------------------------------------------------------------------------
// Launcher
// ---------------------------------------------------------------------------
static void run_inorm_relu(float* buf, int C, int HW)
{
    inorm_stats<<<BATCH * C, 256>>>(buf, HW);
    int total = BATCH * C * HW;
    norm_relu<<<cdiv(total, 256), 256>>>(buf, HW, total);
}

extern "C" void kernel_launch(void* const* d_in, const int* in_sizes, int n_in,
                              void* d_out, int out_size)
{
    const float* x     = (const float*)d_in[0];
    const int*   imap  = (const int*)  d_in[1];
    const float* w_in  = (const float*)d_in[2];
    const float* b_in  = (const float*)d_in[3];
    const float* w_d[4], *b_d[4], *w_u[4], *b_u[4];
    for (int i = 0; i < 4; i++) {
        w_d[i] = (const float*)d_in[4 + 2 * i];
        b_d[i] = (const float*)d_in[5 + 2 * i];
        w_u[i] = (const float*)d_in[12 + 2 * i];
        b_u[i] = (const float*)d_in[13 + 2 * i];
    }
    const float* w_out = (const float*)d_in[20];
    const float* b_out = (const float*)d_in[21];
    float* out = (float*)d_out;

    float* A; float* B;
    cudaGetSymbolAddress((void**)&A, g_bufA);
    cudaGetSymbolAddress((void**)&B, g_bufB);

    // 1) in conv: x -> A, [8,16,512,512]
    {
        int total = BATCH * NF * HH * WW;
        conv7_reflect<<<cdiv(total, 256), 256>>>(x, w_in, b_in, A, CIN, NF, HH, WW, 0);
        run_inorm_relu(A, NF, HH * WW);
    }

    // 2) down path (ping-pong A<->B)
    float* src = A; float* dst = B;
    int C = NF, H = HH, W = WW;
    for (int i = 0; i < 4; i++) {
        int Cout = 2 * C, Ho = H / 2, Wo = W / 2;
        int total = BATCH * Cout * Ho * Wo;
        conv3_s2<<<cdiv(total, 256), 256>>>(src, w_d[i], b_d[i], dst, C, Cout, H, W);
        run_inorm_relu(dst, Cout, Ho * Wo);
        float* t = src; src = dst; dst = t;
        C = Cout; H = Ho; W = Wo;
    }
    // now src holds [8,256,32,32]

    // 3) up path
    for (int i = 0; i < 4; i++) {
        int Cout = C / 2, Ho = 2 * H, Wo = 2 * W;
        int total = BATCH * Cout * Ho * Wo;
        tconv3_s2<<<cdiv(total, 256), 256>>>(src, w_u[i], b_u[i], dst, C, Cout, H, W);
        run_inorm_relu(dst, Cout, Ho * Wo);
        float* t = src; src = dst; dst = t;
        C = Cout; H = Ho; W = Wo;
    }
    // now src holds [8,16,512,512]

    // 4) out conv + tanh: src -> dst, [8,3,512,512]
    {
        int total = BATCH * FEAT * HH * WW;
        conv7_reflect<<<cdiv(total, 256), 256>>>(src, w_out, b_out, dst, NF, FEAT, HH, WW, 1);
    }

    // 5) instance mean pooling: dst + imap -> out
    {
        int HW = HH * WW;
        pool_zero<<<1, 256>>>();
        dim3 grid(128, BATCH);
        pool_partial<<<grid, 256>>>(dst, imap, HW);
        pool_finalize<<<1, 256>>>();
        pool_scatter<<<cdiv(BATCH * HW, 256), 256>>>(imap, out, HW);
    }
}

// round 2
// speedup vs baseline: 6.9531x; 6.9531x over previous
#include <cuda_runtime.h>
#include <math.h>

// ---------------------------------------------------------------------------
// Problem constants
// ---------------------------------------------------------------------------
#define BATCH   8
#define CIN     3
#define HH      512
#define WW      512
#define NF      16
#define FEAT    3
#define NUM_IDS 32
#define EPS     1e-5f

#define BUF_ELEMS (8*16*512*512)

__device__ float g_bufA[BUF_ELEMS];
__device__ float g_bufB[BUF_ELEMS];
__device__ float g_mean[8*256];
__device__ float g_istd[8*256];
__device__ float g_ssum[8*256];
__device__ float g_ssq [8*256];
__device__ float g_sums[BATCH*NUM_IDS*FEAT];
__device__ float g_cnt [BATCH*NUM_IDS];

static inline int cdiv(int a, int b) { return (a + b - 1) / b; }

#define CO_T 8
#define CI_CHUNK 8

// ---------------------------------------------------------------------------
// conv 3x3 stride 2 pad 1, CO_T output channels per thread, 2 pixels/thread.
// Input is RAW previous conv output; norm+relu applied on load.
// ---------------------------------------------------------------------------
__global__ void conv3s2_k(const float* __restrict__ in,
                          const float* __restrict__ mean,
                          const float* __restrict__ istd,
                          const float* __restrict__ w,
                          const float* __restrict__ bias,
                          float* __restrict__ out,
                          int Cin, int Cout, int Hin, int Win)
{
    const int Hout = Hin >> 1, Wout = Win >> 1;
    const int HWo = Hout * Wout;
    const int tid = threadIdx.x;
    const int b = blockIdx.z;
    const int co0 = blockIdx.y * CO_T;
    const int p0 = blockIdx.x * (blockDim.x * 2) + tid * 2;

    const bool valid0 = p0 < HWo;
    const bool valid1 = (p0 + 1) < HWo;
    const int oy0 = p0 / Wout, ox0 = p0 % Wout;
    const int oy1 = (p0 + 1) / Wout, ox1 = (p0 + 1) % Wout;

    float acc[2][CO_T];
#pragma unroll
    for (int px = 0; px < 2; px++)
#pragma unroll
        for (int c = 0; c < CO_T; c++) acc[px][c] = 0.f;

    __shared__ float ws[CI_CHUNK][9][CO_T];

    const float* mrow = mean + b * Cin;
    const float* srow = istd + b * Cin;

    for (int cb = 0; cb < Cin; cb += CI_CHUNK) {
        for (int e = tid; e < CI_CHUNK * 9 * CO_T; e += blockDim.x) {
            int co = e % CO_T;
            int tap = (e / CO_T) % 9;
            int ci = e / (CO_T * 9);
            ws[ci][tap][co] = w[((co0 + co) * Cin + cb + ci) * 9 + tap];
        }
        __syncthreads();

        for (int ci = 0; ci < CI_CHUNK; ci++) {
            const int c = cb + ci;
            const float m = mrow[c], s = srow[c];
            const float* ip = in + ((size_t)(b * Cin + c)) * Hin * Win;
            float v[2][9];
#pragma unroll
            for (int px = 0; px < 2; px++) {
                int oy = px ? oy1 : oy0;
                int ox = px ? ox1 : ox0;
#pragma unroll
                for (int ky = 0; ky < 3; ky++) {
                    int iy = 2 * oy - 1 + ky;
                    bool by = (iy >= 0) && (iy < Hin);
#pragma unroll
                    for (int kx = 0; kx < 3; kx++) {
                        int ix = 2 * ox - 1 + kx;
                        float t = 0.f;
                        if (by && ix >= 0 && ix < Win) {
                            t = __ldg(ip + (size_t)iy * Win + ix);
                            t = fmaxf((t - m) * s, 0.f);
                        }
                        v[px][ky * 3 + kx] = t;
                    }
                }
            }
#pragma unroll
            for (int tap = 0; tap < 9; tap++) {
                const float4 wa = *(const float4*)&ws[ci][tap][0];
                const float4 wb = *(const float4*)&ws[ci][tap][4];
#pragma unroll
                for (int px = 0; px < 2; px++) {
                    const float t = v[px][tap];
                    acc[px][0] += t * wa.x; acc[px][1] += t * wa.y;
                    acc[px][2] += t * wa.z; acc[px][3] += t * wa.w;
                    acc[px][4] += t * wb.x; acc[px][5] += t * wb.y;
                    acc[px][6] += t * wb.z; acc[px][7] += t * wb.w;
                }
            }
        }
        __syncthreads();
    }

#pragma unroll
    for (int co = 0; co < CO_T; co++) {
        float bv = bias[co0 + co];
        size_t base = ((size_t)(b * Cout + co0 + co)) * HWo;
        if (valid0) out[base + p0] = acc[0][co] + bv;
        if (valid1) out[base + p0 + 1] = acc[1][co] + bv;
    }
}

// ---------------------------------------------------------------------------
// ConvTranspose2d k=3 s=2 p=1 op=1 as parity-decomposed quad per thread.
// w in torch layout [Cin, Cout, 3, 3]. Norm+relu on load.
// out(2m,2n)     = w[1][1]*v00
// out(2m,2n+1)  += w[1][0]*v01 + w[1][2]*v00
// out(2m+1,2n)  += w[0][1]*v10 + w[2][1]*v00
// out(2m+1,2n+1)+= w[0][0]*v11 + w[0][2]*v10 + w[2][0]*v01 + w[2][2]*v00
// ---------------------------------------------------------------------------
__global__ void tconv3s2_k(const float* __restrict__ in,
                           const float* __restrict__ mean,
                           const float* __restrict__ istd,
                           const float* __restrict__ w,
                           const float* __restrict__ bias,
                           float* __restrict__ out,
                           int Cin, int Cout, int Hin, int Win)
{
    const int HWi = Hin * Win;
    const int q = blockIdx.x * blockDim.x + threadIdx.x;
    const int b = blockIdx.z;
    const int co0 = blockIdx.y * CO_T;
    const bool valid = q < HWi;
    const int m = valid ? (q / Win) : 0;
    const int n = valid ? (q % Win) : 0;
    const bool hx = (n + 1) < Win;
    const bool hy = (m + 1) < Hin;

    float acc[4][CO_T];
#pragma unroll
    for (int p = 0; p < 4; p++)
#pragma unroll
        for (int c = 0; c < CO_T; c++) acc[p][c] = 0.f;

    __shared__ float ws[CI_CHUNK][9][CO_T];

    const float* mrow = mean + b * Cin;
    const float* srow = istd + b * Cin;

    for (int cb = 0; cb < Cin; cb += CI_CHUNK) {
        for (int e = threadIdx.x; e < CI_CHUNK * 9 * CO_T; e += blockDim.x) {
            int co = e % CO_T;
            int tap = (e / CO_T) % 9;
            int ci = e / (CO_T * 9);
            ws[ci][tap][co] = w[((size_t)(cb + ci) * Cout + co0 + co) * 9 + tap];
        }
        __syncthreads();

        for (int ci = 0; ci < CI_CHUNK; ci++) {
            const int c = cb + ci;
            const float mm = mrow[c], ss = srow[c];
            const float* ip = in + ((size_t)(b * Cin + c)) * HWi;
            float v00 = 0.f, v01 = 0.f, v10 = 0.f, v11 = 0.f;
            if (valid) {
                const float* r0 = ip + (size_t)m * Win;
                v00 = fmaxf((__ldg(r0 + n) - mm) * ss, 0.f);
                if (hx) v01 = fmaxf((__ldg(r0 + n + 1) - mm) * ss, 0.f);
                if (hy) {
                    const float* r1 = r0 + Win;
                    v10 = fmaxf((__ldg(r1 + n) - mm) * ss, 0.f);
                    if (hx) v11 = fmaxf((__ldg(r1 + n + 1) - mm) * ss, 0.f);
                }
            }
            // (tap, quad, val) table; tap = ky*3+kx
            const float vals[9] = {v00, v01, v00, v10, v00, v11, v10, v01, v00};
            const int taps[9]  = {4, 3, 5, 1, 7, 0, 2, 6, 8};
            const int quads[9] = {0, 1, 1, 2, 2, 3, 3, 3, 3};
#pragma unroll
            for (int k = 0; k < 9; k++) {
                const float4 wa = *(const float4*)&ws[ci][taps[k]][0];
                const float4 wb = *(const float4*)&ws[ci][taps[k]][4];
                const float t = vals[k];
                float* a = acc[quads[k]];
                a[0] += t * wa.x; a[1] += t * wa.y; a[2] += t * wa.z; a[3] += t * wa.w;
                a[4] += t * wb.x; a[5] += t * wb.y; a[6] += t * wb.z; a[7] += t * wb.w;
            }
        }
        __syncthreads();
    }

    if (!valid) return;
    const int Hout = 2 * Hin, Wout = 2 * Win;
#pragma unroll
    for (int co = 0; co < CO_T; co++) {
        float bv = bias[co0 + co];
        size_t base = ((size_t)(b * Cout + co0 + co)) * Hout * Wout;
        size_t o00 = base + (size_t)(2 * m) * Wout + 2 * n;
        out[o00]            = acc[0][co] + bv;
        out[o00 + 1]        = acc[1][co] + bv;
        out[o00 + Wout]     = acc[2][co] + bv;
        out[o00 + Wout + 1] = acc[3][co] + bv;
    }
}

// ---------------------------------------------------------------------------
// 7x7 reflect conv, first layer (Cin=3 -> Cout=16). Raw input, no norm.
// 2 pixels per thread (same row), all 16 output channels per thread.
// ---------------------------------------------------------------------------
__device__ __forceinline__ int reflect_idx(int i, int n) {
    return (i < 0) ? -i : ((i >= n) ? 2 * n - 2 - i : i);
}

__global__ void conv7_in_k(const float* __restrict__ in,
                           const float* __restrict__ w,
                           const float* __restrict__ bias,
                           float* __restrict__ out)
{
    const int W = WW, H = HH;
    const int tid = threadIdx.x;
    const int b = blockIdx.y;
    const int p0 = blockIdx.x * 256 + tid * 2;   // 2 adjacent px, same row
    const int oy = p0 / W, ox = p0 % W;

    __shared__ float ws[CIN][49][16];
    for (int e = tid; e < CIN * 49 * 16; e += blockDim.x) {
        int co = e % 16;
        int tap = (e / 16) % 49;
        int ci = e / (16 * 49);
        ws[ci][tap][co] = w[(co * CIN + ci) * 49 + tap];
    }
    __syncthreads();

    float acc[2][16];
#pragma unroll
    for (int px = 0; px < 2; px++)
#pragma unroll
        for (int c = 0; c < 16; c++) acc[px][c] = 0.f;

    for (int ci = 0; ci < CIN; ci++) {
        const float* ip = in + ((size_t)(b * CIN + ci)) * H * W;
#pragma unroll
        for (int ky = 0; ky < 7; ky++) {
            int iy = reflect_idx(oy - 3 + ky, H);
            const float* row = ip + (size_t)iy * W;
            float vv[8];
#pragma unroll
            for (int k = 0; k < 8; k++) {
                int ix = reflect_idx(ox - 3 + k, W);
                vv[k] = __ldg(row + ix);
            }
#pragma unroll
            for (int kx = 0; kx < 7; kx++) {
                const float4 w0 = *(const float4*)&ws[ci][ky * 7 + kx][0];
                const float4 w1 = *(const float4*)&ws[ci][ky * 7 + kx][4];
                const float4 w2 = *(const float4*)&ws[ci][ky * 7 + kx][8];
                const float4 w3 = *(const float4*)&ws[ci][ky * 7 + kx][12];
#pragma unroll
                for (int px = 0; px < 2; px++) {
                    const float t = vv[kx + px];
                    acc[px][0]  += t * w0.x; acc[px][1]  += t * w0.y;
                    acc[px][2]  += t * w0.z; acc[px][3]  += t * w0.w;
                    acc[px][4]  += t * w1.x; acc[px][5]  += t * w1.y;
                    acc[px][6]  += t * w1.z; acc[px][7]  += t * w1.w;
                    acc[px][8]  += t * w2.x; acc[px][9]  += t * w2.y;
                    acc[px][10] += t * w2.z; acc[px][11] += t * w2.w;
                    acc[px][12] += t * w3.x; acc[px][13] += t * w3.y;
                    acc[px][14] += t * w3.z; acc[px][15] += t * w3.w;
                }
            }
        }
    }

#pragma unroll
    for (int co = 0; co < 16; co++) {
        float bv = bias[co];
        size_t base = ((size_t)(b * NF + co)) * H * W;
        out[base + p0] = acc[0][co] + bv;
        out[base + p0 + 1] = acc[1][co] + bv;
    }
}

// ---------------------------------------------------------------------------
// 7x7 reflect conv, last layer (16 -> 3) + tanh. Norm+relu on load.
// One block per output row; 4 pixels per thread, 3 channels.
// ---------------------------------------------------------------------------
__global__ void conv7_out_k(const float* __restrict__ in,
                            const float* __restrict__ mean,
                            const float* __restrict__ istd,
                            const float* __restrict__ w,
                            const float* __restrict__ bias,
                            float* __restrict__ out)
{
    const int W = WW, H = HH;
    const int tid = threadIdx.x;
    const int b = blockIdx.y;
    const int oy = blockIdx.x;       // one row per block (512 rows)
    const int ox0 = tid * 4;

    __shared__ float ws[NF][49][4];  // co padded to 4
    for (int e = tid; e < NF * 49 * 4; e += blockDim.x) {
        int co = e % 4;
        int tap = (e / 4) % 49;
        int ci = e / (4 * 49);
        ws[ci][tap][co] = (co < FEAT) ? w[(co * NF + ci) * 49 + tap] : 0.f;
    }
    __syncthreads();

    float acc[4][3];
#pragma unroll
    for (int px = 0; px < 4; px++)
#pragma unroll
        for (int c = 0; c < 3; c++) acc[px][c] = 0.f;

    const float* mrow = mean + b * NF;
    const float* srow = istd + b * NF;

    for (int ci = 0; ci < NF; ci++) {
        const float m = mrow[ci], s = srow[ci];
        const float* ip = in + ((size_t)(b * NF + ci)) * H * W;
#pragma unroll
        for (int ky = 0; ky < 7; ky++) {
            int iy = reflect_idx(oy - 3 + ky, H);
            const float* row = ip + (size_t)iy * W;
            float vv[10];
#pragma unroll
            for (int k = 0; k < 10; k++) {
                int ix = reflect_idx(ox0 - 3 + k, W);
                vv[k] = fmaxf((__ldg(row + ix) - m) * s, 0.f);
            }
#pragma unroll
            for (int kx = 0; kx < 7; kx++) {
                const float4 wv = *(const float4*)&ws[ci][ky * 7 + kx][0];
#pragma unroll
                for (int px = 0; px < 4; px++) {
                    const float t = vv[kx + px];
                    acc[px][0] += t * wv.x;
                    acc[px][1] += t * wv.y;
                    acc[px][2] += t * wv.z;
                }
            }
        }
    }

#pragma unroll
    for (int co = 0; co < 3; co++) {
        float bv = bias[co];
        size_t base = ((size_t)(b * FEAT + co)) * H * W + (size_t)oy * W;
#pragma unroll
        for (int px = 0; px < 4; px++) {
            out[base + ox0 + px] = tanhf(acc[px][co] + bv);
        }
    }
}

// ---------------------------------------------------------------------------
// InstanceNorm statistics (sum, sumsq) with 2D grid + atomics
// ---------------------------------------------------------------------------
#define STAT_CHUNK 4096

__global__ void stats_zero(int n)
{
    int i = blockIdx.x * blockDim.x + threadIdx.x;
    if (i < n) { g_ssum[i] = 0.f; g_ssq[i] = 0.f; }
}

__global__ void stats_partial(const float* __restrict__ x, int HW)
{
    int bc = blockIdx.x;
    const float* p = x + (size_t)bc * HW;
    int start = blockIdx.y * STAT_CHUNK;
    int end = min(start + STAT_CHUNK, HW);
    float s = 0.f, ss = 0.f;
    for (int i = start + threadIdx.x; i < end; i += blockDim.x) {
        float v = p[i];
        s += v; ss += v * v;
    }
    // warp reduce
#pragma unroll
    for (int off = 16; off > 0; off >>= 1) {
        s += __shfl_down_sync(0xffffffffu, s, off);
        ss += __shfl_down_sync(0xffffffffu, ss, off);
    }
    __shared__ float sh_s[8], sh_ss[8];
    int wid = threadIdx.x >> 5, lid = threadIdx.x & 31;
    if (lid == 0) { sh_s[wid] = s; sh_ss[wid] = ss; }
    __syncthreads();
    if (threadIdx.x == 0) {
        float ts = 0.f, tss = 0.f;
        int nw = blockDim.x >> 5;
        for (int i = 0; i < nw; i++) { ts += sh_s[i]; tss += sh_ss[i]; }
        atomicAdd(&g_ssum[bc], ts);
        atomicAdd(&g_ssq[bc], tss);
    }
}

__global__ void stats_final(int n, int HW)
{
    int i = blockIdx.x * blockDim.x + threadIdx.x;
    if (i >= n) return;
    float m = g_ssum[i] / (float)HW;
    float var = g_ssq[i] / (float)HW - m * m;
    g_mean[i] = m;
    g_istd[i] = rsqrtf(var + EPS);
}

// ---------------------------------------------------------------------------
// Instance pooling
// ---------------------------------------------------------------------------
__global__ void pool_zero()
{
    int i = blockIdx.x * blockDim.x + threadIdx.x;
    if (i < BATCH * NUM_IDS * FEAT) g_sums[i] = 0.f;
    if (i < BATCH * NUM_IDS) g_cnt[i] = 0.f;
}

__global__ void pool_partial(const float* __restrict__ feat,
                             const int* __restrict__ ids, int HW)
{
    __shared__ float s_sum[NUM_IDS * FEAT];
    __shared__ float s_cnt[NUM_IDS];
    for (int i = threadIdx.x; i < NUM_IDS * FEAT; i += blockDim.x) s_sum[i] = 0.f;
    for (int i = threadIdx.x; i < NUM_IDS; i += blockDim.x) s_cnt[i] = 0.f;
    __syncthreads();

    int bb = blockIdx.y;
    for (int p = blockIdx.x * blockDim.x + threadIdx.x; p < HW;
         p += gridDim.x * blockDim.x) {
        int id = ids[(size_t)bb * HW + p];
        atomicAdd(&s_cnt[id], 1.f);
#pragma unroll
        for (int c = 0; c < FEAT; c++) {
            atomicAdd(&s_sum[id * FEAT + c], feat[((size_t)bb * FEAT + c) * HW + p]);
        }
    }
    __syncthreads();
    for (int i = threadIdx.x; i < NUM_IDS * FEAT; i += blockDim.x)
        atomicAdd(&g_sums[bb * NUM_IDS * FEAT + i], s_sum[i]);
    for (int i = threadIdx.x; i < NUM_IDS; i += blockDim.x)
        atomicAdd(&g_cnt[bb * NUM_IDS + i], s_cnt[i]);
}

__global__ void pool_finalize()
{
    int i = blockIdx.x * blockDim.x + threadIdx.x;
    if (i >= BATCH * NUM_IDS) return;
    float c = g_cnt[i];
    float inv = 1.f / fmaxf(c, 1.f);
#pragma unroll
    for (int k = 0; k < FEAT; k++) g_sums[i * FEAT + k] *= inv;
}

__global__ void pool_scatter(const int* __restrict__ ids,
                             float* __restrict__ out, int HW)
{
    int idx = blockIdx.x * blockDim.x + threadIdx.x;
    if (idx >= BATCH * HW) return;
    int p = idx % HW;
    int bb = idx / HW;
    int id = ids[(size_t)bb * HW + p];
#pragma unroll
    for (int c = 0; c < FEAT; c++) {
        out[((size_t)bb * FEAT + c) * HW + p] = g_sums[(bb * NUM_IDS + id) * FEAT + c];
    }
}

// ---------------------------------------------------------------------------
// Launcher
// ---------------------------------------------------------------------------
static void run_stats(const float* buf, int C, int HW)
{
    int n = BATCH * C;
    stats_zero<<<cdiv(n, 256), 256>>>(n);
    dim3 grid(n, cdiv(HW, STAT_CHUNK));
    stats_partial<<<grid, 256>>>(buf, HW);
    stats_final<<<cdiv(n, 256), 256>>>(n, HW);
}

extern "C" void kernel_launch(void* const* d_in, const int* in_sizes, int n_in,
                              void* d_out, int out_size)
{
    const float* x     = (const float*)d_in[0];
    const int*   imap  = (const int*)  d_in[1];
    const float* w_in  = (const float*)d_in[2];
    const float* b_in  = (const float*)d_in[3];
    const float* w_d[4], *b_d[4], *w_u[4], *b_u[4];
    for (int i = 0; i < 4; i++) {
        w_d[i] = (const float*)d_in[4 + 2 * i];
        b_d[i] = (const float*)d_in[5 + 2 * i];
        w_u[i] = (const float*)d_in[12 + 2 * i];
        b_u[i] = (const float*)d_in[13 + 2 * i];
    }
    const float* w_out = (const float*)d_in[20];
    const float* b_out = (const float*)d_in[21];
    float* out = (float*)d_out;

    float* A; float* B;
    cudaGetSymbolAddress((void**)&A, g_bufA);
    cudaGetSymbolAddress((void**)&B, g_bufB);

    float* d_mean; float* d_istd;
    cudaGetSymbolAddress((void**)&d_mean, g_mean);
    cudaGetSymbolAddress((void**)&d_istd, g_istd);

    // 1) in conv: x -> A  [8,16,512,512], raw output; then stats
    {
        dim3 grid(HH * WW / 256, BATCH);
        conv7_in_k<<<grid, 128>>>(x, w_in, b_in, A);
        run_stats(A, NF, HH * WW);
    }

    // 2) down path (ping-pong)
    float* src = A; float* dst = B;
    int C = NF, H = HH, W = WW;
    for (int i = 0; i < 4; i++) {
        int Cout = 2 * C, Ho = H / 2, Wo = W / 2;
        dim3 grid(cdiv(Ho * Wo, 256), Cout / CO_T, BATCH);
        conv3s2_k<<<grid, 128>>>(src, d_mean, d_istd, w_d[i], b_d[i], dst,
                                 C, Cout, H, W);
        run_stats(dst, Cout, Ho * Wo);
        float* t = src; src = dst; dst = t;
        C = Cout; H = Ho; W = Wo;
    }
    // src: [8,256,32,32]

    // 3) up path
    for (int i = 0; i < 4; i++) {
        int Cout = C / 2, Ho = 2 * H, Wo = 2 * W;
        dim3 grid(cdiv(H * W, 128), Cout / CO_T, BATCH);
        tconv3s2_k<<<grid, 128>>>(src, d_mean, d_istd, w_u[i], b_u[i], dst,
                                  C, Cout, H, W);
        run_stats(dst, Cout, Ho * Wo);
        float* t = src; src = dst; dst = t;
        C = Cout; H = Ho; W = Wo;
    }
    // src: [8,16,512,512]

    // 4) out conv + tanh: src -> dst [8,3,512,512]
    {
        dim3 grid(HH, BATCH);
        conv7_out_k<<<grid, 128>>>(src, d_mean, d_istd, w_out, b_out, dst);
    }

    // 5) instance mean pooling
    {
        int HW = HH * WW;
        pool_zero<<<1, 256>>>();
        dim3 grid(128, BATCH);
        pool_partial<<<grid, 256>>>(dst, imap, HW);
        pool_finalize<<<1, 256>>>();
        pool_scatter<<<cdiv(BATCH * HW, 256), 256>>>(imap, out, HW);
    }
}

// round 3
// speedup vs baseline: 7.9824x; 1.1480x over previous
#include <cuda_runtime.h>
#include <math.h>

// ---------------------------------------------------------------------------
#define BATCH   8
#define CIN     3
#define HH      512
#define WW      512
#define NF      16
#define FEAT    3
#define NUM_IDS 32
#define EPS     1e-5f

#define BUF_ELEMS (8*16*512*512)

__device__ float g_bufA[BUF_ELEMS];
__device__ float g_bufB[BUF_ELEMS];
__device__ float g_mean[8*256];
__device__ float g_istd[8*256];
__device__ float g_ssum[8*256];
__device__ float g_ssq [8*256];
__device__ float g_sums[BATCH*NUM_IDS*FEAT];
__device__ float g_cnt [BATCH*NUM_IDS];

static inline int cdiv(int a, int b) { return (a + b - 1) / b; }

#define CO_T 16
#define CI_CHUNK 8

__device__ __forceinline__ float warp_sum(float v) {
    v += __shfl_down_sync(0xffffffffu, v, 16);
    v += __shfl_down_sync(0xffffffffu, v, 8);
    v += __shfl_down_sync(0xffffffffu, v, 4);
    v += __shfl_down_sync(0xffffffffu, v, 2);
    v += __shfl_down_sync(0xffffffffu, v, 1);
    return v;
}

__device__ __forceinline__ int reflect_idx(int i, int n) {
    return (i < 0) ? -i : ((i >= n) ? 2 * n - 2 - i : i);
}

// ---------------------------------------------------------------------------
// conv 3x3 stride 2 pad 1. 16 output channels/thread, 2 same-row pixels.
// Norm+relu applied on load. Stats of output fused into epilogue.
// ---------------------------------------------------------------------------
__global__ __launch_bounds__(128) void conv3s2_k(
    const float* __restrict__ in, const float* __restrict__ w,
    const float* __restrict__ bias, float* __restrict__ out,
    int Cin, int Cout, int Hin, int Win)
{
    const int Hout = Hin >> 1, Wout = Win >> 1;
    const int HWo = Hout * Wout;
    const int tid = threadIdx.x;
    const int b = blockIdx.z;
    const int co0 = blockIdx.y * CO_T;
    const int p0 = blockIdx.x * 256 + tid * 2;
    const bool valid = p0 < HWo;           // HWo even, p0 even -> pair valid
    const int oy = p0 / Wout, ox = p0 % Wout;

    float acc[2][CO_T];
#pragma unroll
    for (int px = 0; px < 2; px++)
#pragma unroll
        for (int c = 0; c < CO_T; c++) acc[px][c] = 0.f;

    __shared__ float ws[CI_CHUNK][9][CO_T];
    __shared__ float red[2 * CO_T];

    for (int cb = 0; cb < Cin; cb += CI_CHUNK) {
        for (int e = tid; e < CI_CHUNK * 9 * CO_T; e += 128) {
            int co = e % CO_T;
            int tap = (e / CO_T) % 9;
            int ci = e / (CO_T * 9);
            ws[ci][tap][co] = w[((co0 + co) * Cin + cb + ci) * 9 + tap];
        }
        __syncthreads();

        for (int ci = 0; ci < CI_CHUNK; ci++) {
            const int c = cb + ci;
            const float m = g_mean[b * Cin + c];
            const float s = g_istd[b * Cin + c];
            const float* ip = in + ((size_t)(b * Cin + c)) * Hin * Win;
            // shared 3x5 input patch (cols 2*ox-1 .. 2*ox+3, always < Win)
            float v[3][5];
#pragma unroll
            for (int ky = 0; ky < 3; ky++) {
                int iy = 2 * oy - 1 + ky;          // max = Hin-1, only iy<0 clamps
                bool by = (iy >= 0) && valid;
                const float* row = ip + (size_t)iy * Win;
#pragma unroll
                for (int j = 0; j < 5; j++) {
                    int ix = 2 * ox - 1 + j;       // max = Win-1, only ix<0 clamps
                    float t = 0.f;
                    if (by && ix >= 0) t = fmaxf((__ldg(row + ix) - m) * s, 0.f);
                    v[ky][j] = t;
                }
            }
#pragma unroll
            for (int ky = 0; ky < 3; ky++)
#pragma unroll
            for (int kx = 0; kx < 3; kx++) {
                const float4 w0 = *(const float4*)&ws[ci][ky * 3 + kx][0];
                const float4 w1 = *(const float4*)&ws[ci][ky * 3 + kx][4];
                const float4 w2 = *(const float4*)&ws[ci][ky * 3 + kx][8];
                const float4 w3 = *(const float4*)&ws[ci][ky * 3 + kx][12];
                const float t0 = v[ky][kx];
                const float t1 = v[ky][kx + 2];
                acc[0][0]  += t0 * w0.x; acc[0][1]  += t0 * w0.y;
                acc[0][2]  += t0 * w0.z; acc[0][3]  += t0 * w0.w;
                acc[0][4]  += t0 * w1.x; acc[0][5]  += t0 * w1.y;
                acc[0][6]  += t0 * w1.z; acc[0][7]  += t0 * w1.w;
                acc[0][8]  += t0 * w2.x; acc[0][9]  += t0 * w2.y;
                acc[0][10] += t0 * w2.z; acc[0][11] += t0 * w2.w;
                acc[0][12] += t0 * w3.x; acc[0][13] += t0 * w3.y;
                acc[0][14] += t0 * w3.z; acc[0][15] += t0 * w3.w;
                acc[1][0]  += t1 * w0.x; acc[1][1]  += t1 * w0.y;
                acc[1][2]  += t1 * w0.z; acc[1][3]  += t1 * w0.w;
                acc[1][4]  += t1 * w1.x; acc[1][5]  += t1 * w1.y;
                acc[1][6]  += t1 * w1.z; acc[1][7]  += t1 * w1.w;
                acc[1][8]  += t1 * w2.x; acc[1][9]  += t1 * w2.y;
                acc[1][10] += t1 * w2.z; acc[1][11] += t1 * w2.w;
                acc[1][12] += t1 * w3.x; acc[1][13] += t1 * w3.y;
                acc[1][14] += t1 * w3.z; acc[1][15] += t1 * w3.w;
            }
        }
        __syncthreads();
    }

    if (tid < 2 * CO_T) red[tid] = 0.f;
    __syncthreads();

    const int lane = tid & 31;
    const size_t obase = ((size_t)(b * Cout + co0)) * HWo;
#pragma unroll
    for (int co = 0; co < CO_T; co++) {
        float bv = __ldg(bias + co0 + co);
        float v0 = acc[0][co] + bv;
        float v1 = acc[1][co] + bv;
        if (valid) {
            out[obase + (size_t)co * HWo + p0]     = v0;
            out[obase + (size_t)co * HWo + p0 + 1] = v1;
        }
        float s = valid ? (v0 + v1) : 0.f;
        float q = valid ? (v0 * v0 + v1 * v1) : 0.f;
        s = warp_sum(s); q = warp_sum(q);
        if (lane == 0) {
            atomicAdd(&red[co], s);
            atomicAdd(&red[CO_T + co], q);
        }
    }
    __syncthreads();
    if (tid < CO_T) {
        atomicAdd(&g_ssum[b * Cout + co0 + tid], red[tid]);
        atomicAdd(&g_ssq [b * Cout + co0 + tid], red[CO_T + tid]);
    }
}

// ---------------------------------------------------------------------------
// ConvTranspose2d k=3 s=2 p=1 op=1, parity-decomposed 2x2 quad per thread,
// 16 output channels. w in torch layout [Cin, Cout, 3, 3]. Stats fused.
// ---------------------------------------------------------------------------
__global__ __launch_bounds__(128) void tconv3s2_k(
    const float* __restrict__ in, const float* __restrict__ w,
    const float* __restrict__ bias, float* __restrict__ out,
    int Cin, int Cout, int Hin, int Win)
{
    const int HWi = Hin * Win;
    const int q = blockIdx.x * blockDim.x + threadIdx.x;
    const int b = blockIdx.z;
    const int co0 = blockIdx.y * CO_T;
    const bool valid = q < HWi;
    const int m = valid ? (q / Win) : 0;
    const int n = valid ? (q % Win) : 0;
    const bool hx = (n + 1) < Win;
    const bool hy = (m + 1) < Hin;

    float acc[4][CO_T];
#pragma unroll
    for (int p = 0; p < 4; p++)
#pragma unroll
        for (int c = 0; c < CO_T; c++) acc[p][c] = 0.f;

    __shared__ float ws[CI_CHUNK][9][CO_T];
    __shared__ float red[2 * CO_T];

    for (int cb = 0; cb < Cin; cb += CI_CHUNK) {
        for (int e = threadIdx.x; e < CI_CHUNK * 9 * CO_T; e += 128) {
            int co = e % CO_T;
            int tap = (e / CO_T) % 9;
            int ci = e / (CO_T * 9);
            ws[ci][tap][co] = w[((size_t)(cb + ci) * Cout + co0 + co) * 9 + tap];
        }
        __syncthreads();

        for (int ci = 0; ci < CI_CHUNK; ci++) {
            const int c = cb + ci;
            const float mm = g_mean[b * Cin + c];
            const float ss = g_istd[b * Cin + c];
            const float* ip = in + ((size_t)(b * Cin + c)) * HWi;
            float v00 = 0.f, v01 = 0.f, v10 = 0.f, v11 = 0.f;
            if (valid) {
                const float* r0 = ip + (size_t)m * Win;
                v00 = fmaxf((__ldg(r0 + n) - mm) * ss, 0.f);
                if (hx) v01 = fmaxf((__ldg(r0 + n + 1) - mm) * ss, 0.f);
                if (hy) {
                    const float* r1 = r0 + Win;
                    v10 = fmaxf((__ldg(r1 + n) - mm) * ss, 0.f);
                    if (hx) v11 = fmaxf((__ldg(r1 + n + 1) - mm) * ss, 0.f);
                }
            }
            const float vals[9] = {v00, v01, v00, v10, v00, v11, v10, v01, v00};
            const int taps[9]  = {4, 3, 5, 1, 7, 0, 2, 6, 8};
            const int quads[9] = {0, 1, 1, 2, 2, 3, 3, 3, 3};
#pragma unroll
            for (int k = 0; k < 9; k++) {
                const float4 w0 = *(const float4*)&ws[ci][taps[k]][0];
                const float4 w1 = *(const float4*)&ws[ci][taps[k]][4];
                const float4 w2 = *(const float4*)&ws[ci][taps[k]][8];
                const float4 w3 = *(const float4*)&ws[ci][taps[k]][12];
                const float t = vals[k];
                float* a = acc[quads[k]];
                a[0]  += t * w0.x; a[1]  += t * w0.y; a[2]  += t * w0.z; a[3]  += t * w0.w;
                a[4]  += t * w1.x; a[5]  += t * w1.y; a[6]  += t * w1.z; a[7]  += t * w1.w;
                a[8]  += t * w2.x; a[9]  += t * w2.y; a[10] += t * w2.z; a[11] += t * w2.w;
                a[12] += t * w3.x; a[13] += t * w3.y; a[14] += t * w3.z; a[15] += t * w3.w;
            }
        }
        __syncthreads();
    }

    if (threadIdx.x < 2 * CO_T) red[threadIdx.x] = 0.f;
    __syncthreads();

    const int Hout = 2 * Hin, Wout = 2 * Win;
    const int lane = threadIdx.x & 31;
#pragma unroll
    for (int co = 0; co < CO_T; co++) {
        float bv = __ldg(bias + co0 + co);
        float o0 = acc[0][co] + bv, o1 = acc[1][co] + bv;
        float o2 = acc[2][co] + bv, o3 = acc[3][co] + bv;
        if (valid) {
            size_t base = ((size_t)(b * Cout + co0 + co)) * Hout * Wout;
            size_t p00 = base + (size_t)(2 * m) * Wout + 2 * n;
            out[p00]            = o0;
            out[p00 + 1]        = o1;
            out[p00 + Wout]     = o2;
            out[p00 + Wout + 1] = o3;
        }
        float s = valid ? (o0 + o1 + o2 + o3) : 0.f;
        float qq = valid ? (o0 * o0 + o1 * o1 + o2 * o2 + o3 * o3) : 0.f;
        s = warp_sum(s); qq = warp_sum(qq);
        if (lane == 0) {
            atomicAdd(&red[co], s);
            atomicAdd(&red[CO_T + co], qq);
        }
    }
    __syncthreads();
    if (threadIdx.x < CO_T) {
        atomicAdd(&g_ssum[b * Cout + co0 + threadIdx.x], red[threadIdx.x]);
        atomicAdd(&g_ssq [b * Cout + co0 + threadIdx.x], red[CO_T + threadIdx.x]);
    }
}

// ---------------------------------------------------------------------------
// 7x7 reflect conv, first layer (3 -> 16), raw input. One row per block,
// 4 px/thread, all 16 channels. Stats fused.
// ---------------------------------------------------------------------------
__global__ __launch_bounds__(128) void conv7_in_k(
    const float* __restrict__ in, const float* __restrict__ w,
    const float* __restrict__ bias, float* __restrict__ out)
{
    const int W = WW, H = HH;
    const int tid = threadIdx.x;
    const int b = blockIdx.y;
    const int oy = blockIdx.x;
    const int ox0 = tid * 4;

    __shared__ float ws[CIN][49][16];
    __shared__ float red[32];
    for (int e = tid; e < CIN * 49 * 16; e += 128) {
        int co = e % 16;
        int tap = (e / 16) % 49;
        int ci = e / (16 * 49);
        ws[ci][tap][co] = w[(co * CIN + ci) * 49 + tap];
    }
    __syncthreads();

    float acc[4][16];
#pragma unroll
    for (int px = 0; px < 4; px++)
#pragma unroll
        for (int c = 0; c < 16; c++) acc[px][c] = 0.f;

    for (int ci = 0; ci < CIN; ci++) {
        const float* ip = in + ((size_t)(b * CIN + ci)) * H * W;
#pragma unroll
        for (int ky = 0; ky < 7; ky++) {
            int iy = reflect_idx(oy - 3 + ky, H);
            const float* row = ip + (size_t)iy * W;
            float vv[10];
#pragma unroll
            for (int k = 0; k < 10; k++) {
                int ix = reflect_idx(ox0 - 3 + k, W);
                vv[k] = __ldg(row + ix);
            }
#pragma unroll
            for (int kx = 0; kx < 7; kx++) {
                const float4 w0 = *(const float4*)&ws[ci][ky * 7 + kx][0];
                const float4 w1 = *(const float4*)&ws[ci][ky * 7 + kx][4];
                const float4 w2 = *(const float4*)&ws[ci][ky * 7 + kx][8];
                const float4 w3 = *(const float4*)&ws[ci][ky * 7 + kx][12];
#pragma unroll
                for (int px = 0; px < 4; px++) {
                    const float t = vv[kx + px];
                    acc[px][0]  += t * w0.x; acc[px][1]  += t * w0.y;
                    acc[px][2]  += t * w0.z; acc[px][3]  += t * w0.w;
                    acc[px][4]  += t * w1.x; acc[px][5]  += t * w1.y;
                    acc[px][6]  += t * w1.z; acc[px][7]  += t * w1.w;
                    acc[px][8]  += t * w2.x; acc[px][9]  += t * w2.y;
                    acc[px][10] += t * w2.z; acc[px][11] += t * w2.w;
                    acc[px][12] += t * w3.x; acc[px][13] += t * w3.y;
                    acc[px][14] += t * w3.z; acc[px][15] += t * w3.w;
                }
            }
        }
    }

    if (tid < 32) red[tid] = 0.f;
    __syncthreads();

    const int lane = tid & 31;
#pragma unroll
    for (int co = 0; co < 16; co++) {
        float bv = __ldg(bias + co);
        float v0 = acc[0][co] + bv, v1 = acc[1][co] + bv;
        float v2 = acc[2][co] + bv, v3 = acc[3][co] + bv;
        size_t base = ((size_t)(b * NF + co)) * H * W + (size_t)oy * W + ox0;
        out[base] = v0; out[base + 1] = v1; out[base + 2] = v2; out[base + 3] = v3;
        float s = v0 + v1 + v2 + v3;
        float q = v0 * v0 + v1 * v1 + v2 * v2 + v3 * v3;
        s = warp_sum(s); q = warp_sum(q);
        if (lane == 0) {
            atomicAdd(&red[co], s);
            atomicAdd(&red[16 + co], q);
        }
    }
    __syncthreads();
    if (tid < 16) {
        atomicAdd(&g_ssum[b * NF + tid], red[tid]);
        atomicAdd(&g_ssq [b * NF + tid], red[16 + tid]);
    }
}

// ---------------------------------------------------------------------------
// 7x7 reflect conv, last layer (16 -> 3) + tanh + FUSED instance pooling.
// One row per block, 4 px/thread. Feature tensor is never materialized.
// ---------------------------------------------------------------------------
__global__ __launch_bounds__(128) void conv7_out_k(
    const float* __restrict__ in, const int* __restrict__ ids,
    const float* __restrict__ w, const float* __restrict__ bias)
{
    const int W = WW, H = HH;
    const int tid = threadIdx.x;
    const int b = blockIdx.y;
    const int oy = blockIdx.x;
    const int ox0 = tid * 4;

    __shared__ float ws[NF][49][4];
    __shared__ float p_sum[NUM_IDS * FEAT];
    __shared__ float p_cnt[NUM_IDS];
    for (int e = tid; e < NF * 49 * 4; e += 128) {
        int co = e % 4;
        int tap = (e / 4) % 49;
        int ci = e / (4 * 49);
        ws[ci][tap][co] = (co < FEAT) ? w[(co * NF + ci) * 49 + tap] : 0.f;
    }
    if (tid < NUM_IDS * FEAT) p_sum[tid] = 0.f;
    if (tid < NUM_IDS) p_cnt[tid] = 0.f;
    __syncthreads();

    float acc[4][3];
#pragma unroll
    for (int px = 0; px < 4; px++)
#pragma unroll
        for (int c = 0; c < 3; c++) acc[px][c] = 0.f;

    for (int ci = 0; ci < NF; ci++) {
        const float m = g_mean[b * NF + ci];
        const float s = g_istd[b * NF + ci];
        const float* ip = in + ((size_t)(b * NF + ci)) * H * W;
#pragma unroll
        for (int ky = 0; ky < 7; ky++) {
            int iy = reflect_idx(oy - 3 + ky, H);
            const float* row = ip + (size_t)iy * W;
            float vv[10];
#pragma unroll
            for (int k = 0; k < 10; k++) {
                int ix = reflect_idx(ox0 - 3 + k, W);
                vv[k] = fmaxf((__ldg(row + ix) - m) * s, 0.f);
            }
#pragma unroll
            for (int kx = 0; kx < 7; kx++) {
                const float4 wv = *(const float4*)&ws[ci][ky * 7 + kx][0];
#pragma unroll
                for (int px = 0; px < 4; px++) {
                    const float t = vv[kx + px];
                    acc[px][0] += t * wv.x;
                    acc[px][1] += t * wv.y;
                    acc[px][2] += t * wv.z;
                }
            }
        }
    }

    // tanh + pool accumulate
    const int* idrow = ids + (size_t)b * H * W + (size_t)oy * W + ox0;
#pragma unroll
    for (int px = 0; px < 4; px++) {
        int id = idrow[px];
        atomicAdd(&p_cnt[id], 1.f);
#pragma unroll
        for (int c = 0; c < 3; c++) {
            float v = tanhf(acc[px][c] + __ldg(bias + c));
            atomicAdd(&p_sum[id * FEAT + c], v);
        }
    }
    __syncthreads();
    if (tid < NUM_IDS * FEAT) atomicAdd(&g_sums[b * NUM_IDS * FEAT + tid], p_sum[tid]);
    if (tid < NUM_IDS) atomicAdd(&g_cnt[b * NUM_IDS + tid], p_cnt[tid]);
}

// ---------------------------------------------------------------------------
// stats finalize: ssum/ssq -> mean/istd, then zero accumulators for next layer
// ---------------------------------------------------------------------------
__global__ void stats_final(int n, int HW)
{
    int i = blockIdx.x * blockDim.x + threadIdx.x;
    if (i >= n) return;
    float m = g_ssum[i] / (float)HW;
    float var = g_ssq[i] / (float)HW - m * m;
    g_mean[i] = m;
    g_istd[i] = rsqrtf(var + EPS);
    g_ssum[i] = 0.f;
    g_ssq[i] = 0.f;
}

// ---------------------------------------------------------------------------
// Pooling tail
// ---------------------------------------------------------------------------
__global__ void pool_zero()
{
    int i = blockIdx.x * blockDim.x + threadIdx.x;
    if (i < BATCH * NUM_IDS * FEAT) g_sums[i] = 0.f;
    if (i < BATCH * NUM_IDS) g_cnt[i] = 0.f;
}

__global__ void pool_finalize()
{
    int i = blockIdx.x * blockDim.x + threadIdx.x;
    if (i >= BATCH * NUM_IDS) return;
    float c = g_cnt[i];
    float inv = 1.f / fmaxf(c, 1.f);
#pragma unroll
    for (int k = 0; k < FEAT; k++) g_sums[i * FEAT + k] *= inv;
}

__global__ void pool_scatter(const int* __restrict__ ids,
                             float* __restrict__ out, int HW)
{
    int idx = blockIdx.x * blockDim.x + threadIdx.x;
    if (idx >= BATCH * HW) return;
    int p = idx % HW;
    int bb = idx / HW;
    int id = ids[(size_t)bb * HW + p];
#pragma unroll
    for (int c = 0; c < FEAT; c++) {
        out[((size_t)bb * FEAT + c) * HW + p] = g_sums[(bb * NUM_IDS + id) * FEAT + c];
    }
}

// ---------------------------------------------------------------------------
// Launcher
// ---------------------------------------------------------------------------
extern "C" void kernel_launch(void* const* d_in, const int* in_sizes, int n_in,
                              void* d_out, int out_size)
{
    const float* x     = (const float*)d_in[0];
    const int*   imap  = (const int*)  d_in[1];
    const float* w_in  = (const float*)d_in[2];
    const float* b_in  = (const float*)d_in[3];
    const float* w_d[4], *b_d[4], *w_u[4], *b_u[4];
    for (int i = 0; i < 4; i++) {
        w_d[i] = (const float*)d_in[4 + 2 * i];
        b_d[i] = (const float*)d_in[5 + 2 * i];
        w_u[i] = (const float*)d_in[12 + 2 * i];
        b_u[i] = (const float*)d_in[13 + 2 * i];
    }
    const float* w_out = (const float*)d_in[20];
    const float* b_out = (const float*)d_in[21];
    float* out = (float*)d_out;

    float* A; float* B;
    cudaGetSymbolAddress((void**)&A, g_bufA);
    cudaGetSymbolAddress((void**)&B, g_bufB);

    pool_zero<<<cdiv(BATCH * NUM_IDS * FEAT, 256), 256>>>();

    // 1) in conv: x -> A  [8,16,512,512] (stats fused)
    {
        dim3 grid(HH, BATCH);
        conv7_in_k<<<grid, 128>>>(x, w_in, b_in, A);
        stats_final<<<1, 128>>>(BATCH * NF, HH * WW);
    }

    // 2) down path
    float* src = A; float* dst = B;
    int C = NF, H = HH, W = WW;
    for (int i = 0; i < 4; i++) {
        int Cout = 2 * C, Ho = H / 2, Wo = W / 2;
        dim3 grid(cdiv(Ho * Wo, 256), Cout / CO_T, BATCH);
        conv3s2_k<<<grid, 128>>>(src, w_d[i], b_d[i], dst, C, Cout, H, W);
        stats_final<<<cdiv(BATCH * Cout, 128), 128>>>(BATCH * Cout, Ho * Wo);
        float* t = src; src = dst; dst = t;
        C = Cout; H = Ho; W = Wo;
    }
    // src: [8,256,32,32]

    // 3) up path
    for (int i = 0; i < 4; i++) {
        int Cout = C / 2, Ho = 2 * H, Wo = 2 * W;
        dim3 grid(cdiv(H * W, 128), Cout / CO_T, BATCH);
        tconv3s2_k<<<grid, 128>>>(src, w_u[i], b_u[i], dst, C, Cout, H, W);
        stats_final<<<cdiv(BATCH * Cout, 128), 128>>>(BATCH * Cout, Ho * Wo);
        float* t = src; src = dst; dst = t;
        C = Cout; H = Ho; W = Wo;
    }
    // src: [8,16,512,512]

    // 4) out conv + tanh + fused pooling (no feat tensor written)
    {
        dim3 grid(HH, BATCH);
        conv7_out_k<<<grid, 128>>>(src, imap, w_out, b_out);
    }

    // 5) finalize + scatter
    pool_finalize<<<1, 256>>>();
    pool_scatter<<<cdiv(BATCH * HH * WW, 256), 256>>>(imap, out, HH * WW);
}